// round 15
// baseline (speedup 1.0000x reference)
#include <cuda_runtime.h>
#include <cuda_fp16.h>
#include <stdint.h>

// MLP_edge on GB300 (sm_103): per-edge gather + 2-layer MLP (64 -> relu -> 1)
//   dif[e] = K_h[src[e]] - Q_h[dst[e]] + P_e[src[e]]
//   out[e] = relu(dif @ W1 + b1) @ W2 + b2
//
// R15: factorized tables (R12) + fp16 storage (R13) + issue-optimized edge
// kernel:
//  * FFMA2 (packed f32x2) dot: 4 packed FMAs/iter instead of 8 scalar.
//  * src/dst packed int2 in smem: one LDS.64 per edge instead of two LDS.
//  * EPB=64 / NITER=2 / __launch_bounds__(256,7): smaller reg footprint,
//    ~87% occupancy for latency absorption.
//  * Prologue in 128-node tiles (782 blocks): smoother wave structure.
// Numerics identical to R13/R14 (measured 4.32e-4).

#define DD      64
#define NODE_H2 1600000                 // 50000 nodes * 32 half2

__device__ __half2 g_kwh[NODE_H2];      // fp16((K+P)@W1 + b1)
__device__ __half2 g_qwh[NODE_H2];      // fp16(Q@W1)

typedef unsigned long long u64;

// ---------------- shared helpers ----------------
#define SWZ(o) ((o) ^ (((o) >> 3) & 0x70))

static __device__ __forceinline__ uint32_t s2u(const void* p) {
    uint32_t a;
    asm("{ .reg .u64 t; cvta.to.shared.u64 t, %1; cvt.u32.u64 %0, t; }"
        : "=r"(a) : "l"(p));
    return a;
}
static __device__ __forceinline__ uint32_t pkh2(float lo_val, float hi_val) {
    uint32_t r;
    asm("cvt.rn.f16x2.f32 %0, %1, %2;" : "=r"(r) : "f"(hi_val), "f"(lo_val));
    return r;
}
static __device__ __forceinline__ u64 pkf2(float lo, float hi) {
    u64 r; asm("mov.b64 %0, {%1, %2};" : "=l"(r) : "f"(lo), "f"(hi)); return r;
}
static __device__ __forceinline__ void fma2(u64& a, u64 d, u64 w) {
    asm("fma.rn.f32x2 %0, %1, %2, %0;" : "+l"(a) : "l"(d), "l"(w));
}
static __device__ __forceinline__ float2 unpkf2(u64 a) {
    float2 f; asm("mov.b64 {%0, %1}, %2;" : "=f"(f.x), "=f"(f.y) : "l"(a));
    return f;
}
static __device__ __forceinline__ void ldm_x4(uint32_t* r, uint32_t addr) {
    asm volatile(
        "ldmatrix.sync.aligned.m8n8.x4.shared.b16 {%0,%1,%2,%3}, [%4];"
        : "=r"(r[0]), "=r"(r[1]), "=r"(r[2]), "=r"(r[3]) : "r"(addr));
}
static __device__ __forceinline__ void mma_f16(
    float* c, const uint32_t* a, uint32_t b0, uint32_t b1)
{
    asm volatile(
        "mma.sync.aligned.m16n8k16.row.col.f32.f16.f16.f32 "
        "{%0,%1,%2,%3}, {%4,%5,%6,%7}, {%8,%9}, {%0,%1,%2,%3};"
        : "+f"(c[0]), "+f"(c[1]), "+f"(c[2]), "+f"(c[3])
        : "r"(a[0]), "r"(a[1]), "r"(a[2]), "r"(a[3]), "r"(b0), "r"(b1));
}

// ---------------- prologue: node GEMMs -> fp16 tables ----------------
// 128-node tiles. grid (ceil(nn/128), 2): y=0 -> KW=(K+P)@W1+b1; y=1 -> QW=Q@W1
#define PN      128
#define PA_OFF  0                       // A tile: 128 rows x 128B = 16 KB
#define PB_OFF  16384                   // W1^T fp16: 8 KB
#define PB1_OFF 24576                   // b1: 256 B
#define PSMEM   (PB1_OFF + 256)

__global__ void __launch_bounds__(256) node_gemm_kernel(
    const float* __restrict__ Kh, const float* __restrict__ Pe,
    const float* __restrict__ Qh,
    const float* __restrict__ W1, const float* __restrict__ b1, int nn)
{
    extern __shared__ __align__(1024) char smem[];
    const uint32_t su = s2u(smem);
    float* b1s = (float*)(smem + PB1_OFF);

    const int tid   = threadIdx.x;
    const int lane  = tid & 31;
    const int warp  = tid >> 5;
    const int table = blockIdx.y;
    const int n0    = blockIdx.x * PN;

    // stage B = W1^T fp16 (swizzled 128B rows)
    #pragma unroll
    for (int idx = tid; idx < DD * DD; idx += 256) {
        int k = idx >> 6;
        int n = idx & 63;
        uint32_t sw = SWZ((uint32_t)(n * 128 + k * 2));
        *(__half*)(smem + PB_OFF + sw) = __float2half_rn(W1[idx]);
    }
    if (tid < DD) b1s[tid] = b1[tid];

    // stage A = node rows (clamped), fp16
    {
        const int c  = tid & 15;        // float4 chunk
        const int er = tid >> 4;
        #pragma unroll 4
        for (int p = 0; p < 8; p++) {
            int row = er + p * 16;
            int n   = n0 + row;
            if (n >= nn) n = nn - 1;
            float4 v;
            if (table == 0) {
                float4 k4 = ((const float4*)Kh)[n * 16 + c];
                float4 p4 = ((const float4*)Pe)[n * 16 + c];
                v = make_float4(k4.x + p4.x, k4.y + p4.y, k4.z + p4.z, k4.w + p4.w);
            } else {
                v = ((const float4*)Qh)[n * 16 + c];
            }
            uint2 hv;
            hv.x = pkh2(v.x, v.y);
            hv.y = pkh2(v.z, v.w);
            *(uint2*)(smem + PA_OFF + SWZ((uint32_t)(row * 128 + c * 8))) = hv;
        }
    }
    __syncthreads();

    __half2* dstT = (table == 0) ? g_kwh : g_qwh;

    // one m16 tile per warp (8 warps x 16 rows = 128)
    {
        const int mrow0 = warp * 16;

        float acc[8][4];
        #pragma unroll
        for (int nt = 0; nt < 8; nt++)
            #pragma unroll
            for (int i = 0; i < 4; i++) acc[nt][i] = 0.0f;

        #pragma unroll
        for (int k = 0; k < 4; k++) {
            const int arow  = mrow0 + (lane & 15);
            const int acolb = k * 32 + (lane >> 4) * 16;
            uint32_t av[4];
            ldm_x4(av, su + PA_OFF + SWZ((uint32_t)(arow * 128 + acolb)));
            const int brow = lane & 15;
            #pragma unroll
            for (int p = 0; p < 4; p++) {
                uint32_t bv[4];
                ldm_x4(bv, su + PB_OFF + SWZ((uint32_t)((p * 16 + brow) * 128 + acolb)));
                mma_f16(acc[2*p  ], av, bv[0], bv[2]);
                mma_f16(acc[2*p+1], av, bv[1], bv[3]);
            }
        }

        // store rows as fp16 pairs, fold b1 for table 0
        const int r  = lane >> 2;
        const int n1 = n0 + mrow0 + r;
        const int n2 = n1 + 8;
        #pragma unroll
        for (int nt = 0; nt < 8; nt++) {
            int col = nt * 8 + (lane & 3) * 2;
            float bx = 0.0f, by = 0.0f;
            if (table == 0) { bx = b1s[col]; by = b1s[col + 1]; }
            if (n1 < nn) {
                uint32_t h = pkh2(acc[nt][0] + bx, acc[nt][1] + by);
                *(uint32_t*)(dstT + (size_t)n1 * 32 + (col >> 1)) = h;
            }
            if (n2 < nn) {
                uint32_t h = pkh2(acc[nt][2] + bx, acc[nt][3] + by);
                *(uint32_t*)(dstT + (size_t)n2 * 32 + (col >> 1)) = h;
            }
        }
    }
}

// ---------------- main: per-edge score ----------------
// EPB=64 edges/block, 8 lanes/edge, hoisted gathers (MLP=4), FFMA2 dot.
#define EPB   64
#define NITER 2

__global__ void __launch_bounds__(256, 7) edge_score_kernel(
    const int* __restrict__ src, const int* __restrict__ dst,
    const float* __restrict__ W2, const float* __restrict__ b2,
    float* __restrict__ out, int E)
{
    __shared__ float4 w2s[16];
    __shared__ int2   eidx[EPB];

    const int tid = threadIdx.x;
    if (tid < 16) w2s[tid] = ((const float4*)W2)[tid];
    if (tid < 128) {                    // coalesced index staging, int2-packed
        int t  = tid & 63;
        int e  = blockIdx.x * EPB + t;
        int eC = (e < E) ? e : (E - 1);
        if (tid < 64) eidx[t].x = __ldg(src + eC);
        else          eidx[t].y = __ldg(dst + eC);
    }
    __syncthreads();

    const int c    = tid & 7;            // chunk lane: channels c*8 .. c*8+7
    const int slot = tid >> 3;           // 0..31 edge slot
    const float4 wA = w2s[c * 2];
    const float4 wB = w2s[c * 2 + 1];
    const u64 wp0 = pkf2(wA.x, wA.y);
    const u64 wp1 = pkf2(wA.z, wA.w);
    const u64 wp2 = pkf2(wB.x, wB.y);
    const u64 wp3 = pkf2(wB.z, wB.w);
    const float b2v = __ldg(b2);
    const int base  = blockIdx.x * EPB;

    const uint4* kwt = (const uint4*)g_kwh;   // 8 uint4 per node row
    const uint4* qwt = (const uint4*)g_qwh;

    // ---- hoisted gathers: 4 independent LDG.128 in flight ----
    uint4 kv[NITER], qv[NITER];
    #pragma unroll
    for (int it = 0; it < NITER; it++) {
        int2 sd = eidx[slot + it * 32];       // one LDS.64, 8-lane broadcast
        kv[it] = __ldg(kwt + (size_t)sd.x * 8 + c);
        qv[it] = __ldg(qwt + (size_t)sd.y * 8 + c);
    }

    // ---- compute + reduce + store ----
    const __half2 z = __floats2half2_rn(0.0f, 0.0f);
    #pragma unroll
    for (int it = 0; it < NITER; it++) {
        __half2 h0 = __hmax2(__hsub2(*(__half2*)&kv[it].x, *(__half2*)&qv[it].x), z);
        __half2 h1 = __hmax2(__hsub2(*(__half2*)&kv[it].y, *(__half2*)&qv[it].y), z);
        __half2 h2 = __hmax2(__hsub2(*(__half2*)&kv[it].z, *(__half2*)&qv[it].z), z);
        __half2 h3 = __hmax2(__hsub2(*(__half2*)&kv[it].w, *(__half2*)&qv[it].w), z);

        float2 f0 = __half22float2(h0);
        float2 f1 = __half22float2(h1);
        float2 f2 = __half22float2(h2);
        float2 f3 = __half22float2(h3);

        u64 acc = pkf2(0.0f, 0.0f);
        fma2(acc, pkf2(f0.x, f0.y), wp0);
        fma2(acc, pkf2(f1.x, f1.y), wp1);
        fma2(acc, pkf2(f2.x, f2.y), wp2);
        fma2(acc, pkf2(f3.x, f3.y), wp3);
        float2 rr = unpkf2(acc);
        float t = rr.x + rr.y;

        // reduce over the 8 chunk lanes (xor-closed groups: masks 1,2,4)
        t += __shfl_xor_sync(0xffffffffu, t, 1);
        t += __shfl_xor_sync(0xffffffffu, t, 2);
        t += __shfl_xor_sync(0xffffffffu, t, 4);

        int e = base + slot + it * 32;
        if (c == 0 && e < E) out[e] = t + b2v;
    }
}

extern "C" void kernel_launch(void* const* d_in, const int* in_sizes, int n_in,
                              void* d_out, int out_size)
{
    const float* Kh = (const float*)d_in[0];
    const float* Qh = (const float*)d_in[1];
    const float* Pe = (const float*)d_in[2];
    const int*   src = (const int*)d_in[3];
    const int*   dst = (const int*)d_in[4];
    const float* W1 = (const float*)d_in[5];
    const float* b1 = (const float*)d_in[6];
    const float* W2 = (const float*)d_in[7];
    const float* b2 = (const float*)d_in[8];
    float* out = (float*)d_out;

    const int E  = in_sizes[3];
    const int nn = in_sizes[0] / DD;    // node count

    // prologue: node GEMMs into fp16 tables
    cudaFuncSetAttribute(node_gemm_kernel,
                         cudaFuncAttributeMaxDynamicSharedMemorySize, PSMEM);
    dim3 pgrid((nn + PN - 1) / PN, 2);
    node_gemm_kernel<<<pgrid, 256, PSMEM>>>(Kh, Pe, Qh, W1, b1, nn);

    // main: per-edge scores
    const int grid = (E + EPB - 1) / EPB;
    edge_score_kernel<<<grid, 256>>>(src, dst, W2, b2, out, E);
}

// round 16
// speedup vs baseline: 1.1395x; 1.1395x over previous
#include <cuda_runtime.h>
#include <cuda_fp16.h>
#include <stdint.h>

// MLP_edge on GB300 (sm_103): per-edge gather + 2-layer MLP (64 -> relu -> 1)
//   dif[e] = K_h[src[e]] - Q_h[dst[e]] + P_e[src[e]]
//   out[e] = relu(dif @ W1 + b1) @ W2 + b2
//
// R16 = R14 (best: 31.4us) + edge-kernel instruction diet.
//  * Tables: KW[n]=fp16((K+P)@W1+b1), QW[n]=fp16(Q@W1)  (R12/R13, validated)
//  * Edge kernel: EPB=128, NITER=4, hoisted gathers (MLP=8) -- the R14
//    config; R15 proved MLP=8 beats higher occupancy with MLP=4.
//  * NEW: dot product via HFMA2 with fp16 weights (one half2 accumulator),
//    single fp32 conversion at the end: ~10 fewer instr/iter.
//    Error budget: +3.4e-4 abs (fp16 partial sums) on top of measured
//    4.32e-4 -> ~5.5e-4 < 1e-3.
//  * Index staging int2-packed (one LDS.64 per edge).

#define DD      64
#define NODE_H2 1600000                 // 50000 nodes * 32 half2

__device__ __half2 g_kwh[NODE_H2];      // fp16((K+P)@W1 + b1)
__device__ __half2 g_qwh[NODE_H2];      // fp16(Q@W1)

// ---------------- shared helpers ----------------
#define SWZ(o) ((o) ^ (((o) >> 3) & 0x70))

static __device__ __forceinline__ uint32_t s2u(const void* p) {
    uint32_t a;
    asm("{ .reg .u64 t; cvta.to.shared.u64 t, %1; cvt.u32.u64 %0, t; }"
        : "=r"(a) : "l"(p));
    return a;
}
static __device__ __forceinline__ uint32_t pkh2(float lo_val, float hi_val) {
    uint32_t r;
    asm("cvt.rn.f16x2.f32 %0, %1, %2;" : "=r"(r) : "f"(hi_val), "f"(lo_val));
    return r;
}
static __device__ __forceinline__ void ldm_x4(uint32_t* r, uint32_t addr) {
    asm volatile(
        "ldmatrix.sync.aligned.m8n8.x4.shared.b16 {%0,%1,%2,%3}, [%4];"
        : "=r"(r[0]), "=r"(r[1]), "=r"(r[2]), "=r"(r[3]) : "r"(addr));
}
static __device__ __forceinline__ void mma_f16(
    float* c, const uint32_t* a, uint32_t b0, uint32_t b1)
{
    asm volatile(
        "mma.sync.aligned.m16n8k16.row.col.f32.f16.f16.f32 "
        "{%0,%1,%2,%3}, {%4,%5,%6,%7}, {%8,%9}, {%0,%1,%2,%3};"
        : "+f"(c[0]), "+f"(c[1]), "+f"(c[2]), "+f"(c[3])
        : "r"(a[0]), "r"(a[1]), "r"(a[2]), "r"(a[3]), "r"(b0), "r"(b1));
}

// ---------------- prologue: node GEMMs -> fp16 tables (R14-proven) ----------
// grid (ceil(nn/256), 2): y=0 -> KW = (K+P)@W1 + b1 ; y=1 -> QW = Q@W1
#define PA_OFF  0                       // A tile: 256 rows x 128B = 32 KB
#define PB_OFF  32768                   // W1^T fp16: 8 KB
#define PB1_OFF 40960                   // b1: 256 B
#define PSMEM   (PB1_OFF + 256)

__global__ void __launch_bounds__(256) node_gemm_kernel(
    const float* __restrict__ Kh, const float* __restrict__ Pe,
    const float* __restrict__ Qh,
    const float* __restrict__ W1, const float* __restrict__ b1, int nn)
{
    extern __shared__ __align__(1024) char smem[];
    const uint32_t su = s2u(smem);
    float* b1s = (float*)(smem + PB1_OFF);

    const int tid   = threadIdx.x;
    const int lane  = tid & 31;
    const int warp  = tid >> 5;
    const int table = blockIdx.y;
    const int n0    = blockIdx.x * 256;

    // stage B = W1^T fp16 (swizzled 128B rows)
    #pragma unroll
    for (int idx = tid; idx < DD * DD; idx += 256) {
        int k = idx >> 6;
        int n = idx & 63;
        uint32_t sw = SWZ((uint32_t)(n * 128 + k * 2));
        *(__half*)(smem + PB_OFF + sw) = __float2half_rn(W1[idx]);
    }
    if (tid < DD) b1s[tid] = b1[tid];

    // stage A = node rows (clamped), fp16
    {
        const int c  = tid & 15;        // float4 chunk
        const int er = tid >> 4;
        #pragma unroll 4
        for (int p = 0; p < 16; p++) {
            int row = er + p * 16;
            int n   = n0 + row;
            if (n >= nn) n = nn - 1;
            float4 v;
            if (table == 0) {
                float4 k4 = ((const float4*)Kh)[n * 16 + c];
                float4 p4 = ((const float4*)Pe)[n * 16 + c];
                v = make_float4(k4.x + p4.x, k4.y + p4.y, k4.z + p4.z, k4.w + p4.w);
            } else {
                v = ((const float4*)Qh)[n * 16 + c];
            }
            uint2 hv;
            hv.x = pkh2(v.x, v.y);
            hv.y = pkh2(v.z, v.w);
            *(uint2*)(smem + PA_OFF + SWZ((uint32_t)(row * 128 + c * 8))) = hv;
        }
    }
    __syncthreads();

    __half2* dstT = (table == 0) ? g_kwh : g_qwh;

    #pragma unroll
    for (int mt = 0; mt < 2; mt++) {
        const int mrow0 = warp * 32 + mt * 16;

        float acc[8][4];
        #pragma unroll
        for (int nt = 0; nt < 8; nt++)
            #pragma unroll
            for (int i = 0; i < 4; i++) acc[nt][i] = 0.0f;

        #pragma unroll
        for (int k = 0; k < 4; k++) {
            const int arow  = mrow0 + (lane & 15);
            const int acolb = k * 32 + (lane >> 4) * 16;
            uint32_t av[4];
            ldm_x4(av, su + PA_OFF + SWZ((uint32_t)(arow * 128 + acolb)));
            const int brow = lane & 15;
            #pragma unroll
            for (int p = 0; p < 4; p++) {
                uint32_t bv[4];
                ldm_x4(bv, su + PB_OFF + SWZ((uint32_t)((p * 16 + brow) * 128 + acolb)));
                mma_f16(acc[2*p  ], av, bv[0], bv[2]);
                mma_f16(acc[2*p+1], av, bv[1], bv[3]);
            }
        }

        // store rows as fp16 pairs, fold b1 for table 0
        const int r  = lane >> 2;
        const int n1 = n0 + mrow0 + r;
        const int n2 = n1 + 8;
        #pragma unroll
        for (int nt = 0; nt < 8; nt++) {
            int col = nt * 8 + (lane & 3) * 2;
            float bx = 0.0f, by = 0.0f;
            if (table == 0) { bx = b1s[col]; by = b1s[col + 1]; }
            if (n1 < nn) {
                uint32_t h = pkh2(acc[nt][0] + bx, acc[nt][1] + by);
                *(uint32_t*)(dstT + (size_t)n1 * 32 + (col >> 1)) = h;
            }
            if (n2 < nn) {
                uint32_t h = pkh2(acc[nt][2] + bx, acc[nt][3] + by);
                *(uint32_t*)(dstT + (size_t)n2 * 32 + (col >> 1)) = h;
            }
        }
    }
}

// ---------------- main: per-edge score ----------------
// EPB=128, 8 lanes/edge, hoisted gathers (MLP=8), HFMA2 dot w/ fp16 weights.
#define EPB   128
#define NITER 4          // EPB / 32 slots

__global__ void __launch_bounds__(256) edge_score_kernel(
    const int* __restrict__ src, const int* __restrict__ dst,
    const float* __restrict__ W2, const float* __restrict__ b2,
    float* __restrict__ out, int E)
{
    __shared__ float4 w2s[16];
    __shared__ int2   eidx[EPB];

    const int tid = threadIdx.x;
    if (tid < 16) w2s[tid] = ((const float4*)W2)[tid];
    {   // coalesced index staging, int2-packed: 0-127 -> .x(src), 128-255 -> .y(dst)
        int t  = tid & 127;
        int e  = blockIdx.x * EPB + t;
        int eC = (e < E) ? e : (E - 1);
        if (tid < 128) eidx[t].x = __ldg(src + eC);
        else           eidx[t].y = __ldg(dst + eC);
    }
    __syncthreads();

    const int c    = tid & 7;            // chunk lane: channels c*8 .. c*8+7
    const int slot = tid >> 3;           // 0..31 edge slot
    const float4 wA = w2s[c * 2];
    const float4 wB = w2s[c * 2 + 1];
    // fp16 weight pairs for HFMA2 dot
    uint32_t wh0 = pkh2(wA.x, wA.y);
    uint32_t wh1 = pkh2(wA.z, wA.w);
    uint32_t wh2 = pkh2(wB.x, wB.y);
    uint32_t wh3 = pkh2(wB.z, wB.w);
    const float b2v = __ldg(b2);
    const int base  = blockIdx.x * EPB;

    const uint4* kwt = (const uint4*)g_kwh;   // 8 uint4 per node row
    const uint4* qwt = (const uint4*)g_qwh;

    // ---- hoisted gathers: 8 independent LDG.128 in flight ----
    uint4 kv[NITER], qv[NITER];
    #pragma unroll
    for (int it = 0; it < NITER; it++) {
        int2 sd = eidx[slot + it * 32];       // one LDS.64, 8-lane broadcast
        kv[it] = __ldg(kwt + (size_t)sd.x * 8 + c);
        qv[it] = __ldg(qwt + (size_t)sd.y * 8 + c);
    }

    // ---- compute + reduce + store ----
    const __half2 z = __floats2half2_rn(0.0f, 0.0f);
    #pragma unroll
    for (int it = 0; it < NITER; it++) {
        __half2 h0 = __hmax2(__hsub2(*(__half2*)&kv[it].x, *(__half2*)&qv[it].x), z);
        __half2 h1 = __hmax2(__hsub2(*(__half2*)&kv[it].y, *(__half2*)&qv[it].y), z);
        __half2 h2 = __hmax2(__hsub2(*(__half2*)&kv[it].z, *(__half2*)&qv[it].z), z);
        __half2 h3 = __hmax2(__hsub2(*(__half2*)&kv[it].w, *(__half2*)&qv[it].w), z);

        // fp16 dot: one half2 accumulator (even channels in .lo, odd in .hi)
        __half2 acc = __hfma2(h0, *(__half2*)&wh0, z);
        acc = __hfma2(h1, *(__half2*)&wh1, acc);
        acc = __hfma2(h2, *(__half2*)&wh2, acc);
        acc = __hfma2(h3, *(__half2*)&wh3, acc);
        float2 rr = __half22float2(acc);
        float t = rr.x + rr.y;

        // reduce over the 8 chunk lanes (xor-closed groups: masks 1,2,4)
        t += __shfl_xor_sync(0xffffffffu, t, 1);
        t += __shfl_xor_sync(0xffffffffu, t, 2);
        t += __shfl_xor_sync(0xffffffffu, t, 4);

        int e = base + slot + it * 32;
        if (c == 0 && e < E) out[e] = t + b2v;
    }
}

extern "C" void kernel_launch(void* const* d_in, const int* in_sizes, int n_in,
                              void* d_out, int out_size)
{
    const float* Kh = (const float*)d_in[0];
    const float* Qh = (const float*)d_in[1];
    const float* Pe = (const float*)d_in[2];
    const int*   src = (const int*)d_in[3];
    const int*   dst = (const int*)d_in[4];
    const float* W1 = (const float*)d_in[5];
    const float* b1 = (const float*)d_in[6];
    const float* W2 = (const float*)d_in[7];
    const float* b2 = (const float*)d_in[8];
    float* out = (float*)d_out;

    const int E  = in_sizes[3];
    const int nn = in_sizes[0] / DD;    // node count

    // prologue: node GEMMs into fp16 tables
    cudaFuncSetAttribute(node_gemm_kernel,
                         cudaFuncAttributeMaxDynamicSharedMemorySize, PSMEM);
    dim3 pgrid((nn + 255) / 256, 2);
    node_gemm_kernel<<<pgrid, 256, PSMEM>>>(Kh, Pe, Qh, W1, b1, nn);

    // main: per-edge scores
    const int grid = (E + EPB - 1) / EPB;
    edge_score_kernel<<<grid, 256>>>(src, dst, W2, b2, out, E);
}